// round 5
// baseline (speedup 1.0000x reference)
#include <cuda_runtime.h>

// Grid: 128^3 cells, cell = (bin+64), idx = x + 128*y + 16384*z
// Each cell: float4 {sum_x, sum_y, sum_z, count}
#define D    128
#define D3   (128*128*128)
#define OFF  64
#define NMAX 200704

__device__ float4 g_gridA[D3];     // scatter ping
__device__ float4 g_gridB[D3];     // scatter pong
__device__ float4 g_grid1[D3];     // conv output / gather source
__device__ float  g_Xbuf[2][NMAX * 3];
__device__ int    g_actA[16 * 128];   // activity flag per (ytile=y>>3, z)
__device__ int    g_actB[16 * 128];
__device__ unsigned g_maxd2_bits;
__device__ int g_done;

// ---------------------------------------------------------------- helpers
__device__ __forceinline__ int bin_of(float v) {
    // match jnp: (X / 0.1f).astype(int32) == IEEE RN divide, trunc toward zero
    int b = (int)__fdiv_rn(v, 0.1f);
    b += OFF;
    return min(max(b, 0), D - 1);
}

__device__ __forceinline__ void fma4(float4& a, float w, const float4 v) {
    a.x += w * v.x; a.y += w * v.y; a.z += w * v.z; a.w += w * v.w;
}

__device__ __forceinline__ void red4(float4* p, float x, float y, float z, float w) {
    asm volatile("red.global.add.v4.f32 [%0], {%1, %2, %3, %4};"
                 :: "l"(p), "f"(x), "f"(y), "f"(z), "f"(w) : "memory");
}

// ---------------------------------------------------------------- initial scatter (step 0 only)
// ILP=4: 4 independent points per thread for memory-level parallelism.
__global__ void scatter0_kernel(const float* __restrict__ X, int n) {
    int base = blockIdx.x * (blockDim.x * 4) + threadIdx.x;
#pragma unroll
    for (int j = 0; j < 4; j++) {
        int i = base + j * 256;
        if (i < n) {
            float x = X[3 * i + 0];
            float y = X[3 * i + 1];
            float z = X[3 * i + 2];
            int yb = bin_of(y), zb = bin_of(z);
            int cell = bin_of(x) + (yb << 7) + (zb << 14);
            g_actA[((yb >> 3) << 7) + zb] = 1;
            red4(&g_gridA[cell], x, y, z, 1.0f);
        }
    }
}

// ---------------------------------------------------------------- fused 3D separable conv
// weights [1,2,3,2,1] per axis. Block: full x-line (128) x 4 output y-rows,
// z-seg of 8. 512 blocks x 512 threads -> 2 blocks/SM (barrier overlap).
// Window trimmed by activity flags. Folds convergence bookkeeping (block 0).

__device__ __forceinline__ void load_slice(const float4* __restrict__ src,
                                           int zc, int x, int r, int y0,
                                           float4& a, float4& b) {
    int zoff = (min(max(zc, 0), D - 1)) << 14;
    int ya = min(max(y0 + r - 2, 0), D - 1);
    a = src[x + (ya << 7) + zoff];
    int yb = min(max(y0 + r + 2, 0), D - 1);
    b = src[x + (yb << 7) + zoff];
}

__global__ __launch_bounds__(512) void conv3d_kernel(int sel, int first) {
    __shared__ float4 raw[8][D];
    __shared__ float4 xf[8][D];
    __shared__ unsigned s_mask;

    if (blockIdx.x == 0 && threadIdx.x == 0) {
        // fold convergence check: uses previous step's max displacement^2
        if (first) g_done = 0;
        else if (__uint_as_float(g_maxd2_bits) <= 1e-6f) g_done = 1;
        g_maxd2_bits = 0u;
    }

    const float4* __restrict__ src = sel ? g_gridB : g_gridA;
    const int* __restrict__ act = sel ? g_actB : g_actA;

    int x = threadIdx.x & 127;
    int r = threadIdx.x >> 7;            // 0..3
    int yq = blockIdx.x & 31;            // 32 y-quads of 4 rows
    int z0 = (blockIdx.x >> 5) << 3;     // 16 z-segments of 8 slices
    int y0 = yq << 2;
    int yt = y0 >> 3;                    // activity tile (8-row granularity)

    if (threadIdx.x < 32) {
        int f = (threadIdx.x < 8) ? act[(yt << 7) + z0 + threadIdx.x] : 0;
        unsigned bm = __ballot_sync(0xffffffffu, f != 0);
        if (threadIdx.x == 0) s_mask = bm;
    }
    __syncthreads();
    unsigned need = s_mask;
    if (!need) return;
    int zlo = z0 + __ffs(need) - 1;
    int zhi = z0 + 31 - __clz(need);
    int nslices = zhi - zlo + 5;         // raw slices zlo-2 .. zhi+2

    const float W0 = 1.f, W1 = 2.f, W2 = 3.f, W3 = 2.f, W4 = 1.f;

    float4 r0, r1, r2, r3, r4;           // z ring
    r0 = r1 = r2 = r3 = r4 = make_float4(0.f, 0.f, 0.f, 0.f);

    float4 pa, pb;                       // prefetch regs (rows r, r+4)
    load_slice(src, zlo - 2, x, r, y0, pa, pb);

#pragma unroll 1
    for (int zi = 0; zi < nslices; zi++) {
        int zc = zlo - 2 + zi;
        raw[r][x] = pa;
        raw[r + 4][x] = pb;
        __syncthreads();

        if (zi < nslices - 1) load_slice(src, zc + 1, x, r, y0, pa, pb);

        // x-filter: rows r and r+4
        {
            int xm2 = max(x - 2, 0), xm1 = max(x - 1, 0);
            int xp1 = min(x + 1, D - 1), xp2 = min(x + 2, D - 1);
            float4 a = make_float4(0.f, 0.f, 0.f, 0.f);
            fma4(a, W0, raw[r][xm2]); fma4(a, W1, raw[r][xm1]);
            fma4(a, W2, raw[r][x]);   fma4(a, W3, raw[r][xp1]);
            fma4(a, W4, raw[r][xp2]);
            xf[r][x] = a;
            float4 b = make_float4(0.f, 0.f, 0.f, 0.f);
            fma4(b, W0, raw[r + 4][xm2]); fma4(b, W1, raw[r + 4][xm1]);
            fma4(b, W2, raw[r + 4][x]);   fma4(b, W3, raw[r + 4][xp1]);
            fma4(b, W4, raw[r + 4][xp2]);
            xf[r + 4][x] = b;
        }
        __syncthreads();

        // y-filter for output row (global y = y0 + r): xf rows r..r+4
        float4 a = make_float4(0.f, 0.f, 0.f, 0.f);
        fma4(a, W0, xf[r + 0][x]);
        fma4(a, W1, xf[r + 1][x]);
        fma4(a, W2, xf[r + 2][x]);
        fma4(a, W3, xf[r + 3][x]);
        fma4(a, W4, xf[r + 4][x]);

        r0 = r1; r1 = r2; r2 = r3; r3 = r4; r4 = a;

        if (zi >= 4) {
            int zo = zc - 2;             // zlo .. zhi
            float4 o;
            o.x = r0.x + 2.f * r1.x + 3.f * r2.x + 2.f * r3.x + r4.x;
            o.y = r0.y + 2.f * r1.y + 3.f * r2.y + 2.f * r3.y + r4.y;
            o.z = r0.z + 2.f * r1.z + 3.f * r2.z + 2.f * r3.z + r4.z;
            o.w = r0.w + 2.f * r1.w + 3.f * r2.w + 2.f * r3.w + r4.w;
            g_grid1[x + ((y0 + r) << 7) + (zo << 14)] = o;
        }
        // no third sync: next raw store races only with xf reads (disjoint arrays)
    }
}

// ---------------------------------------------------------------- fused gather + scatter(next)
// ILP=4: 4 independent gather/scatter chains per thread.
__global__ void fused_gs_kernel(const float* __restrict__ Xext, int srcSel,
                                float* __restrict__ Oext, int dstSel,
                                int gsel, int doScatter, int n) {
    __shared__ float s_max[8];
    const float* X = (srcSel < 0) ? Xext : g_Xbuf[srcSel];
    float* Y = (dstSel < 0) ? Oext : g_Xbuf[dstSel];
    float4* gOld = gsel ? g_gridB : g_gridA;   // consumed this step -> zero
    float4* gNew = gsel ? g_gridA : g_gridB;   // next step's scatter target
    int* actOld = gsel ? g_actB : g_actA;
    int* actNew = gsel ? g_actA : g_actB;

    int done = g_done;
    int base = blockIdx.x * (blockDim.x * 4) + threadIdx.x;
    float d2 = 0.f;
#pragma unroll
    for (int j = 0; j < 4; j++) {
        int i = base + j * 256;
        if (i < n) {
            float x = X[3 * i + 0];
            float y = X[3 * i + 1];
            float z = X[3 * i + 2];
            int yb = bin_of(y), zb = bin_of(z);
            int cell = bin_of(x) + (yb << 7) + (zb << 14);
            float4 t = g_grid1[cell];
            // undo this step's scatter: keeps grids & flags all-zero at boundaries
            gOld[cell] = make_float4(0.f, 0.f, 0.f, 0.f);
            actOld[((yb >> 3) << 7) + zb] = 0;
            float nx = __fdiv_rn(t.x, t.w);
            float ny = __fdiv_rn(t.y, t.w);
            float nz = __fdiv_rn(t.z, t.w);
            if (done) { nx = x; ny = y; nz = z; }
            Y[3 * i + 0] = nx;
            Y[3 * i + 1] = ny;
            Y[3 * i + 2] = nz;
            float dx = nx - x, dy = ny - y, dz = nz - z;
            d2 = fmaxf(d2, dx * dx + dy * dy + dz * dz);
            if (doScatter) {
                int nyb = bin_of(ny), nzb = bin_of(nz);
                int ncell = bin_of(nx) + (nyb << 7) + (nzb << 14);
                actNew[((nyb >> 3) << 7) + nzb] = 1;
                red4(&gNew[ncell], nx, ny, nz, 1.0f);
            }
        }
    }
#pragma unroll
    for (int o = 16; o > 0; o >>= 1)
        d2 = fmaxf(d2, __shfl_xor_sync(0xFFFFFFFFu, d2, o));
    int wid = threadIdx.x >> 5;
    if ((threadIdx.x & 31) == 0) s_max[wid] = d2;
    __syncthreads();
    if (threadIdx.x < 8) {
        float v = s_max[threadIdx.x];
#pragma unroll
        for (int o = 4; o > 0; o >>= 1)
            v = fmaxf(v, __shfl_xor_sync(0xFFu, v, o));
        if (threadIdx.x == 0)
            atomicMax(&g_maxd2_bits, __float_as_uint(v));
    }
}

// ---------------------------------------------------------------- launch
extern "C" void kernel_launch(void* const* d_in, const int* in_sizes, int n_in,
                              void* d_out, int out_size) {
    const float* Xin = (const float*)d_in[0];
    float* Out = (float*)d_out;
    int n = in_sizes[0] / 3;

    int pblocks = (n + 1023) / 1024;     // 256 threads x 4 points
    int srcSel[5] = {-1, 0, 1, 0, 1};
    int dstSel[5] = { 0, 1, 0, 1, -1};

    scatter0_kernel<<<pblocks, 256>>>(Xin, n);
    for (int s = 0; s < 5; s++) {
        int gsel = s & 1;
        conv3d_kernel<<<512, 512>>>(gsel, s == 0);
        fused_gs_kernel<<<pblocks, 256>>>(Xin, srcSel[s], Out, dstSel[s],
                                          gsel, s < 4, n);
    }
}

// round 6
// speedup vs baseline: 1.1558x; 1.1558x over previous
#include <cuda_runtime.h>

// Grid: 128^3 cells, cell = (bin+64), idx = x + 128*y + 16384*z
// Each cell: float4 {sum_x, sum_y, sum_z, count}
#define D    128
#define D3   (128*128*128)
#define OFF  64
#define NMAX 200704

__device__ float4 g_gridA[D3];     // scatter ping
__device__ float4 g_gridB[D3];     // scatter pong
__device__ float4 g_grid1[D3];     // conv output / gather source
__device__ float  g_Xbuf[2][NMAX * 3];
__device__ int    g_actA[16 * 128];   // activity flag per (ytile=y>>3, z)
__device__ int    g_actB[16 * 128];
__device__ unsigned g_maxd2_bits;
__device__ int g_done;

// ---------------------------------------------------------------- helpers
__device__ __forceinline__ int bin_of(float v) {
    // match jnp: (X / 0.1f).astype(int32) == IEEE RN divide, trunc toward zero
    int b = (int)__fdiv_rn(v, 0.1f);
    b += OFF;
    return min(max(b, 0), D - 1);
}

__device__ __forceinline__ void fma4(float4& a, float w, const float4 v) {
    a.x += w * v.x; a.y += w * v.y; a.z += w * v.z; a.w += w * v.w;
}

__device__ __forceinline__ void red4(float4* p, float x, float y, float z, float w) {
    asm volatile("red.global.add.v4.f32 [%0], {%1, %2, %3, %4};"
                 :: "l"(p), "f"(x), "f"(y), "f"(z), "f"(w) : "memory");
}

// ---------------------------------------------------------------- initial scatter (step 0 only)
__global__ void scatter0_kernel(const float* __restrict__ X, int n) {
    int i = blockIdx.x * blockDim.x + threadIdx.x;
    if (i >= n) return;
    float x = X[3 * i + 0];
    float y = X[3 * i + 1];
    float z = X[3 * i + 2];
    int yb = bin_of(y), zb = bin_of(z);
    int cell = bin_of(x) + (yb << 7) + (zb << 14);
    g_actA[((yb >> 3) << 7) + zb] = 1;
    red4(&g_gridA[cell], x, y, z, 1.0f);
}

// ---------------------------------------------------------------- fused 3D separable conv
// weights [1,2,3,2,1] per axis. Block: 64-wide x half-line x 8 output y-rows,
// z-seg of 8. 512 blocks x 512 threads, <=64 regs -> 2 blocks/SM so barrier
// stalls of one block are hidden by the other. Window trimmed by activity
// flags. Folds convergence bookkeeping (block 0).
//
// smem rows are 68 wide (64 core + 2 halo each side). Thread (r, xl):
//  - loads raw col xl+2 (global x0+xl) for rows r and r+8 (r<4)
//  - xl<2  additionally loads left halo col xl   (global x0-2+xl, clamped)
//  - xl>=62 additionally loads right halo col xl+4 (global x0+2+xl, clamped)
//  - x-filters rows r and r+8 (r<4) at core col xl
//  - y-filters output row y0+r, z-ring, writes slice z-2

__global__ __launch_bounds__(512, 2) void conv3d_kernel(int sel, int first) {
    __shared__ float4 raw[12][68];
    __shared__ float4 xf[12][64];
    __shared__ unsigned s_mask;

    if (blockIdx.x == 0 && threadIdx.x == 0) {
        if (first) g_done = 0;
        else if (__uint_as_float(g_maxd2_bits) <= 1e-6f) g_done = 1;
        g_maxd2_bits = 0u;
    }

    const float4* __restrict__ src = sel ? g_gridB : g_gridA;
    const int* __restrict__ act = sel ? g_actB : g_actA;

    int xl = threadIdx.x & 63;           // 0..63
    int r  = threadIdx.x >> 6;           // 0..7
    int xh = blockIdx.x & 1;             // x half
    int yt = (blockIdx.x >> 1) & 15;     // 16 y-tiles of 8 rows
    int z0 = (blockIdx.x >> 5) << 3;     // 16 z-segments of 8 slices
    int x0 = xh << 6;
    int y0 = yt << 3;

    if (threadIdx.x < 32) {
        int f = (threadIdx.x < 8) ? act[(yt << 7) + z0 + threadIdx.x] : 0;
        unsigned bm = __ballot_sync(0xffffffffu, f != 0);
        if (threadIdx.x == 0) s_mask = bm;
    }
    __syncthreads();
    unsigned need = s_mask;
    if (!need) return;
    int zlo = z0 + __ffs(need) - 1;
    int zhi = z0 + 31 - __clz(need);
    int nslices = zhi - zlo + 5;         // raw slices zlo-2 .. zhi+2

    // per-thread global x columns
    int gx  = x0 + xl;                               // core column
    bool hasHalo = (xl < 2) || (xl >= 62);
    int hcol = (xl < 2) ? xl : (xl + 4);             // smem halo col
    int hgx  = (xl < 2) ? (x0 - 2 + xl) : (x0 + 2 + xl);
    hgx = min(max(hgx, 0), D - 1);

    // smem row indices this thread fills: rows r and (r<4 ? r+8 : none)
    int ya1 = min(max(y0 + r - 2, 0), D - 1);
    int ya2 = min(max(y0 + r + 6, 0), D - 1);

    const float W0 = 1.f, W1 = 2.f, W2 = 3.f, W3 = 2.f, W4 = 1.f;

    float4 r0, r1, r2, r3, r4;           // z ring
    r0 = r1 = r2 = r3 = r4 = make_float4(0.f, 0.f, 0.f, 0.f);

    float4 pa, pb, ph1, ph2;             // prefetch regs
    {
        int zoff = (min(max(zlo - 2, 0), D - 1)) << 14;
        pa = src[gx + (ya1 << 7) + zoff];
        pb = src[gx + (ya2 << 7) + zoff];
        if (hasHalo) {
            ph1 = src[hgx + (ya1 << 7) + zoff];
            ph2 = src[hgx + (ya2 << 7) + zoff];
        }
    }

#pragma unroll 1
    for (int zi = 0; zi < nslices; zi++) {
        int zc = zlo - 2 + zi;
        raw[r][xl + 2] = pa;
        if (r < 4) raw[r + 8][xl + 2] = pb;
        if (hasHalo) {
            raw[r][hcol] = ph1;
            if (r < 4) raw[r + 8][hcol] = ph2;
        }
        __syncthreads();

        if (zi < nslices - 1) {
            int zoff = (min(max(zc + 1, 0), D - 1)) << 14;
            pa = src[gx + (ya1 << 7) + zoff];
            pb = src[gx + (ya2 << 7) + zoff];
            if (hasHalo) {
                ph1 = src[hgx + (ya1 << 7) + zoff];
                ph2 = src[hgx + (ya2 << 7) + zoff];
            }
        }

        // x-filter at core col xl: raw window [xl, xl+4]
        {
            float4 a = make_float4(0.f, 0.f, 0.f, 0.f);
            fma4(a, W0, raw[r][xl]);     fma4(a, W1, raw[r][xl + 1]);
            fma4(a, W2, raw[r][xl + 2]); fma4(a, W3, raw[r][xl + 3]);
            fma4(a, W4, raw[r][xl + 4]);
            xf[r][xl] = a;
            if (r < 4) {
                float4 b = make_float4(0.f, 0.f, 0.f, 0.f);
                fma4(b, W0, raw[r + 8][xl]);     fma4(b, W1, raw[r + 8][xl + 1]);
                fma4(b, W2, raw[r + 8][xl + 2]); fma4(b, W3, raw[r + 8][xl + 3]);
                fma4(b, W4, raw[r + 8][xl + 4]);
                xf[r + 8][xl] = b;
            }
        }
        __syncthreads();

        // y-filter for output row (global y = y0 + r): xf rows r..r+4
        float4 a = make_float4(0.f, 0.f, 0.f, 0.f);
        fma4(a, W0, xf[r + 0][xl]);
        fma4(a, W1, xf[r + 1][xl]);
        fma4(a, W2, xf[r + 2][xl]);
        fma4(a, W3, xf[r + 3][xl]);
        fma4(a, W4, xf[r + 4][xl]);

        r0 = r1; r1 = r2; r2 = r3; r3 = r4; r4 = a;

        if (zi >= 4) {
            int zo = zc - 2;             // zlo .. zhi
            float4 o;
            o.x = r0.x + 2.f * r1.x + 3.f * r2.x + 2.f * r3.x + r4.x;
            o.y = r0.y + 2.f * r1.y + 3.f * r2.y + 2.f * r3.y + r4.y;
            o.z = r0.z + 2.f * r1.z + 3.f * r2.z + 2.f * r3.z + r4.z;
            o.w = r0.w + 2.f * r1.w + 3.f * r2.w + 2.f * r3.w + r4.w;
            g_grid1[gx + ((y0 + r) << 7) + (zo << 14)] = o;
        }
        // no third sync: next raw store races only with xf reads (disjoint arrays)
    }
}

// ---------------------------------------------------------------- fused gather + scatter(next)
// 1 point per thread (max warp-level parallelism: 200k chains = 200k threads).
__global__ void fused_gs_kernel(const float* __restrict__ Xext, int srcSel,
                                float* __restrict__ Oext, int dstSel,
                                int gsel, int doScatter, int n) {
    __shared__ float s_max[8];
    const float* X = (srcSel < 0) ? Xext : g_Xbuf[srcSel];
    float* Y = (dstSel < 0) ? Oext : g_Xbuf[dstSel];
    float4* gOld = gsel ? g_gridB : g_gridA;   // consumed this step -> zero
    float4* gNew = gsel ? g_gridA : g_gridB;   // next step's scatter target
    int* actOld = gsel ? g_actB : g_actA;
    int* actNew = gsel ? g_actA : g_actB;

    int i = blockIdx.x * blockDim.x + threadIdx.x;
    float d2 = 0.f;
    if (i < n) {
        float x = X[3 * i + 0];
        float y = X[3 * i + 1];
        float z = X[3 * i + 2];
        int yb = bin_of(y), zb = bin_of(z);
        int cell = bin_of(x) + (yb << 7) + (zb << 14);
        float4 t = g_grid1[cell];
        // undo this step's scatter: keeps grids & flags all-zero at boundaries
        gOld[cell] = make_float4(0.f, 0.f, 0.f, 0.f);
        actOld[((yb >> 3) << 7) + zb] = 0;
        float nx = __fdiv_rn(t.x, t.w);
        float ny = __fdiv_rn(t.y, t.w);
        float nz = __fdiv_rn(t.z, t.w);
        if (g_done) { nx = x; ny = y; nz = z; }
        Y[3 * i + 0] = nx;
        Y[3 * i + 1] = ny;
        Y[3 * i + 2] = nz;
        float dx = nx - x, dy = ny - y, dz = nz - z;
        d2 = dx * dx + dy * dy + dz * dz;
        if (doScatter) {
            int nyb = bin_of(ny), nzb = bin_of(nz);
            int ncell = bin_of(nx) + (nyb << 7) + (nzb << 14);
            actNew[((nyb >> 3) << 7) + nzb] = 1;
            red4(&gNew[ncell], nx, ny, nz, 1.0f);
        }
    }
#pragma unroll
    for (int o = 16; o > 0; o >>= 1)
        d2 = fmaxf(d2, __shfl_xor_sync(0xFFFFFFFFu, d2, o));
    int wid = threadIdx.x >> 5;
    if ((threadIdx.x & 31) == 0) s_max[wid] = d2;
    __syncthreads();
    if (threadIdx.x < 8) {
        float v = s_max[threadIdx.x];
#pragma unroll
        for (int o = 4; o > 0; o >>= 1)
            v = fmaxf(v, __shfl_xor_sync(0xFFu, v, o));
        if (threadIdx.x == 0)
            atomicMax(&g_maxd2_bits, __float_as_uint(v));
    }
}

// ---------------------------------------------------------------- launch
extern "C" void kernel_launch(void* const* d_in, const int* in_sizes, int n_in,
                              void* d_out, int out_size) {
    const float* Xin = (const float*)d_in[0];
    float* Out = (float*)d_out;
    int n = in_sizes[0] / 3;

    int pblocks = (n + 255) / 256;
    int srcSel[5] = {-1, 0, 1, 0, 1};
    int dstSel[5] = { 0, 1, 0, 1, -1};

    scatter0_kernel<<<pblocks, 256>>>(Xin, n);
    for (int s = 0; s < 5; s++) {
        int gsel = s & 1;
        conv3d_kernel<<<512, 512>>>(gsel, s == 0);
        fused_gs_kernel<<<pblocks, 256>>>(Xin, srcSel[s], Out, dstSel[s],
                                          gsel, s < 4, n);
    }
}

// round 7
// speedup vs baseline: 1.1643x; 1.0074x over previous
#include <cuda_runtime.h>

// Grid: 128^3 cells, cell = (bin+64), idx = x + 128*y + 16384*z
// Each cell: float4 {sum_x, sum_y, sum_z, count}
#define D    128
#define D3   (128*128*128)
#define OFF  64
#define NMAX 200704

__device__ float4 g_gridA[D3];     // scatter ping
__device__ float4 g_gridB[D3];     // scatter pong
__device__ float4 g_grid1[D3];     // conv output / gather source
__device__ float  g_Xbuf[2][NMAX * 3];
__device__ int    g_actA[16 * 128];   // activity flag per (ytile=y>>3, z)
__device__ int    g_actB[16 * 128];
__device__ unsigned g_maxd2_bits;
__device__ int g_done;

// ---------------------------------------------------------------- helpers
__device__ __forceinline__ int bin_of(float v) {
    // match jnp: (X / 0.1f).astype(int32) == IEEE RN divide, trunc toward zero
    int b = (int)__fdiv_rn(v, 0.1f);
    b += OFF;
    return min(max(b, 0), D - 1);
}

__device__ __forceinline__ void fma4(float4& a, float w, const float4 v) {
    a.x += w * v.x; a.y += w * v.y; a.z += w * v.z; a.w += w * v.w;
}

__device__ __forceinline__ void red4(float4* p, float x, float y, float z, float w) {
    asm volatile("red.global.add.v4.f32 [%0], {%1, %2, %3, %4};"
                 :: "l"(p), "f"(x), "f"(y), "f"(z), "f"(w) : "memory");
}

__device__ __forceinline__ float4 shfl_up4(float4 v, int d) {
    float4 o;
    o.x = __shfl_up_sync(0xffffffffu, v.x, d);
    o.y = __shfl_up_sync(0xffffffffu, v.y, d);
    o.z = __shfl_up_sync(0xffffffffu, v.z, d);
    o.w = __shfl_up_sync(0xffffffffu, v.w, d);
    return o;
}
__device__ __forceinline__ float4 shfl_dn4(float4 v, int d) {
    float4 o;
    o.x = __shfl_down_sync(0xffffffffu, v.x, d);
    o.y = __shfl_down_sync(0xffffffffu, v.y, d);
    o.z = __shfl_down_sync(0xffffffffu, v.z, d);
    o.w = __shfl_down_sync(0xffffffffu, v.w, d);
    return o;
}

// x-filter [1,2,3,2,1] at column x from register v, neighbors via shuffle,
// warp-boundary lanes patched from the raw smem row.
__device__ __forceinline__ float4 xfilt(float4 v, const float4* rowp, int x, int lane) {
    float4 vm1 = shfl_up4(v, 1);
    float4 vm2 = shfl_up4(v, 2);
    float4 vp1 = shfl_dn4(v, 1);
    float4 vp2 = shfl_dn4(v, 2);
    if (lane < 2) {
        vm2 = rowp[max(x - 2, 0)];
        if (lane == 0) vm1 = rowp[max(x - 1, 0)];
    }
    if (lane >= 30) {
        vp2 = rowp[min(x + 2, D - 1)];
        if (lane == 31) vp1 = rowp[min(x + 1, D - 1)];
    }
    float4 a;
    a.x = vm2.x + 2.f * vm1.x + 3.f * v.x + 2.f * vp1.x + vp2.x;
    a.y = vm2.y + 2.f * vm1.y + 3.f * v.y + 2.f * vp1.y + vp2.y;
    a.z = vm2.z + 2.f * vm1.z + 3.f * v.z + 2.f * vp1.z + vp2.z;
    a.w = vm2.w + 2.f * vm1.w + 3.f * v.w + 2.f * vp1.w + vp2.w;
    return a;
}

// ---------------------------------------------------------------- initial scatter (step 0 only)
__global__ void scatter0_kernel(const float* __restrict__ X, int n) {
    int i = blockIdx.x * blockDim.x + threadIdx.x;
    if (i >= n) return;
    float x = X[3 * i + 0];
    float y = X[3 * i + 1];
    float z = X[3 * i + 2];
    int yb = bin_of(y), zb = bin_of(z);
    int cell = bin_of(x) + (yb << 7) + (zb << 14);
    g_actA[((yb >> 3) << 7) + zb] = 1;
    red4(&g_gridA[cell], x, y, z, 1.0f);
}

// ---------------------------------------------------------------- fused 3D separable conv
// weights [1,2,3,2,1] per axis. Block: full x-line (128) x 8 output y-rows,
// z-seg of 8. 256 blocks x 1024 threads (R4 geometry). x-filter done in
// registers via warp shuffles (x == lane dimension); raw smem kept only for
// warp-boundary patches. Smem ops/thread/slice: ~8.3 vs 15.5 before.

__device__ __forceinline__ void load_slice(const float4* __restrict__ src,
                                           int zc, int x, int r, int y0,
                                           float4& a, float4& b) {
    int zoff = (min(max(zc, 0), D - 1)) << 14;
    int ya = min(max(y0 + r - 2, 0), D - 1);
    a = src[x + (ya << 7) + zoff];
    if (r < 4) {
        int yb = min(max(y0 + r + 6, 0), D - 1);
        b = src[x + (yb << 7) + zoff];
    }
}

__global__ __launch_bounds__(1024) void conv3d_kernel(int sel, int first) {
    __shared__ float4 raw[12][D];
    __shared__ float4 xf[12][D];
    __shared__ unsigned s_mask;

    if (blockIdx.x == 0 && threadIdx.x == 0) {
        // fold convergence check: uses previous step's max displacement^2
        if (first) g_done = 0;
        else if (__uint_as_float(g_maxd2_bits) <= 1e-6f) g_done = 1;
        g_maxd2_bits = 0u;
    }

    const float4* __restrict__ src = sel ? g_gridB : g_gridA;
    const int* __restrict__ act = sel ? g_actB : g_actA;

    int x = threadIdx.x & 127;
    int lane = threadIdx.x & 31;
    int r = threadIdx.x >> 7;            // 0..7
    int yt = blockIdx.x & 15;            // 16 y-tiles of 8 rows
    int z0 = (blockIdx.x >> 4) << 3;     // 16 z-segments of 8 slices
    int y0 = yt << 3;

    if (threadIdx.x < 32) {
        int f = (threadIdx.x < 8) ? act[(yt << 7) + z0 + threadIdx.x] : 0;
        unsigned bm = __ballot_sync(0xffffffffu, f != 0);
        if (threadIdx.x == 0) s_mask = bm;
    }
    __syncthreads();
    unsigned need = s_mask;
    if (!need) return;
    int zlo = z0 + __ffs(need) - 1;
    int zhi = z0 + 31 - __clz(need);
    int nslices = zhi - zlo + 5;         // raw slices zlo-2 .. zhi+2

    float4 r0, r1, r2, r3, r4;           // z ring
    r0 = r1 = r2 = r3 = r4 = make_float4(0.f, 0.f, 0.f, 0.f);

    float4 pa, pb;                       // current slice values (rows r, r+8)
    load_slice(src, zlo - 2, x, r, y0, pa, pb);

#pragma unroll 1
    for (int zi = 0; zi < nslices; zi++) {
        int zc = zlo - 2 + zi;
        raw[r][x] = pa;
        if (r < 4) raw[r + 8][x] = pb;
        __syncthreads();                 // raw visible for boundary patches

        // x-filter in registers (shuffles), boundary lanes patch from raw
        float4 xa = xfilt(pa, raw[r], x, lane);
        xf[r][x] = xa;
        if (r < 4) {
            float4 xb = xfilt(pb, raw[r + 8], x, lane);
            xf[r + 8][x] = xb;
        }

        // prefetch next slice (pa/pb free now)
        if (zi < nslices - 1) load_slice(src, zc + 1, x, r, y0, pa, pb);

        __syncthreads();                 // xf visible

        // y-filter for output row (global y = y0 + r): xf rows r..r+4
        float4 a = make_float4(0.f, 0.f, 0.f, 0.f);
        fma4(a, 1.f, xf[r + 0][x]);
        fma4(a, 2.f, xf[r + 1][x]);
        fma4(a, 3.f, xf[r + 2][x]);
        fma4(a, 2.f, xf[r + 3][x]);
        fma4(a, 1.f, xf[r + 4][x]);

        r0 = r1; r1 = r2; r2 = r3; r3 = r4; r4 = a;

        if (zi >= 4) {
            int zo = zc - 2;             // zlo .. zhi
            float4 o;
            o.x = r0.x + 2.f * r1.x + 3.f * r2.x + 2.f * r3.x + r4.x;
            o.y = r0.y + 2.f * r1.y + 3.f * r2.y + 2.f * r3.y + r4.y;
            o.z = r0.z + 2.f * r1.z + 3.f * r2.z + 2.f * r3.z + r4.z;
            o.w = r0.w + 2.f * r1.w + 3.f * r2.w + 2.f * r3.w + r4.w;
            g_grid1[x + ((y0 + r) << 7) + (zo << 14)] = o;
        }
        // raw store of next iter vs this iter's patch reads: ordered by the
        // xf-sync plus the fact that every warp's patch reads precede it.
    }
}

// ---------------------------------------------------------------- fused gather + scatter(next)
// 1 point per thread (max warp-level parallelism).
__global__ void fused_gs_kernel(const float* __restrict__ Xext, int srcSel,
                                float* __restrict__ Oext, int dstSel,
                                int gsel, int doScatter, int n) {
    __shared__ float s_max[8];
    const float* X = (srcSel < 0) ? Xext : g_Xbuf[srcSel];
    float* Y = (dstSel < 0) ? Oext : g_Xbuf[dstSel];
    float4* gOld = gsel ? g_gridB : g_gridA;   // consumed this step -> zero
    float4* gNew = gsel ? g_gridA : g_gridB;   // next step's scatter target
    int* actOld = gsel ? g_actB : g_actA;
    int* actNew = gsel ? g_actA : g_actB;

    int i = blockIdx.x * blockDim.x + threadIdx.x;
    float d2 = 0.f;
    if (i < n) {
        float x = X[3 * i + 0];
        float y = X[3 * i + 1];
        float z = X[3 * i + 2];
        int yb = bin_of(y), zb = bin_of(z);
        int cell = bin_of(x) + (yb << 7) + (zb << 14);
        float4 t = g_grid1[cell];
        // undo this step's scatter: keeps grids & flags all-zero at boundaries
        gOld[cell] = make_float4(0.f, 0.f, 0.f, 0.f);
        actOld[((yb >> 3) << 7) + zb] = 0;
        float nx = __fdiv_rn(t.x, t.w);
        float ny = __fdiv_rn(t.y, t.w);
        float nz = __fdiv_rn(t.z, t.w);
        if (g_done) { nx = x; ny = y; nz = z; }
        Y[3 * i + 0] = nx;
        Y[3 * i + 1] = ny;
        Y[3 * i + 2] = nz;
        float dx = nx - x, dy = ny - y, dz = nz - z;
        d2 = dx * dx + dy * dy + dz * dz;
        if (doScatter) {
            int nyb = bin_of(ny), nzb = bin_of(nz);
            int ncell = bin_of(nx) + (nyb << 7) + (nzb << 14);
            actNew[((nyb >> 3) << 7) + nzb] = 1;
            red4(&gNew[ncell], nx, ny, nz, 1.0f);
        }
    }
#pragma unroll
    for (int o = 16; o > 0; o >>= 1)
        d2 = fmaxf(d2, __shfl_xor_sync(0xFFFFFFFFu, d2, o));
    int wid = threadIdx.x >> 5;
    if ((threadIdx.x & 31) == 0) s_max[wid] = d2;
    __syncthreads();
    if (threadIdx.x < 8) {
        float v = s_max[threadIdx.x];
#pragma unroll
        for (int o = 4; o > 0; o >>= 1)
            v = fmaxf(v, __shfl_xor_sync(0xFFu, v, o));
        if (threadIdx.x == 0)
            atomicMax(&g_maxd2_bits, __float_as_uint(v));
    }
}

// ---------------------------------------------------------------- launch
extern "C" void kernel_launch(void* const* d_in, const int* in_sizes, int n_in,
                              void* d_out, int out_size) {
    const float* Xin = (const float*)d_in[0];
    float* Out = (float*)d_out;
    int n = in_sizes[0] / 3;

    int pblocks = (n + 255) / 256;
    int srcSel[5] = {-1, 0, 1, 0, 1};
    int dstSel[5] = { 0, 1, 0, 1, -1};

    scatter0_kernel<<<pblocks, 256>>>(Xin, n);
    for (int s = 0; s < 5; s++) {
        int gsel = s & 1;
        conv3d_kernel<<<256, 1024>>>(gsel, s == 0);
        fused_gs_kernel<<<pblocks, 256>>>(Xin, srcSel[s], Out, dstSel[s],
                                          gsel, s < 4, n);
    }
}